// round 16
// baseline (speedup 1.0000x reference)
#include <cuda_runtime.h>
#include <cuda_fp16.h>
#include <math.h>
#include <stdint.h>

// Problem constants
#define B_   16
#define C_   512
#define SP_  1024          // R*R
#define HN_  8
#define D_   128
#define NEG_INF -3.4e38f
// x is [16, 512, 96, 96]

// ---------------- scratch (static device arrays; no allocation) -------------
__device__ float  g_qpool [B_*C_*SP_];      // fp32, residual + attn resid input
__device__ __half g_qpoolh[B_*C_*SP_];      // fp16 GEMM operand
__device__ __half g_kpoolh[B_*C_*SP_];
__device__ __half g_vpoolh[B_*C_*SP_];
__device__ __half g_Qth[B_*HN_*D_*C_];      // [z][e*512 + c]
__device__ __half g_Kth[B_*HN_*D_*C_];
__device__ __half g_Sh [B_*HN_*C_*C_];      // exp(scaled scores)*2^-4, [z][c*512+e]
__device__ __half g_Wvh [C_*C_];
__device__ __half g_Wqkh[HN_*D_*D_];
__device__ float  g_kmean[B_*HN_*D_];       // row sums of Kt (over c), fp32
__device__ float  g_sumexp[B_*HN_*C_];      // per-(z,c) sum of exp*2^-4, fp32
__device__ float  g_rowscale[B_*HN_*C_];

// ---------------- helpers ----------------------------------------------------
__device__ __forceinline__ void mma_f16(float* d, const uint32_t* a, const uint32_t* b) {
    asm volatile("mma.sync.aligned.m16n8k16.row.col.f32.f16.f16.f32 "
        "{%0,%1,%2,%3}, {%4,%5,%6,%7}, {%8,%9}, {%0,%1,%2,%3};"
        : "+f"(d[0]), "+f"(d[1]), "+f"(d[2]), "+f"(d[3])
        : "r"(a[0]), "r"(a[1]), "r"(a[2]), "r"(a[3]), "r"(b[0]), "r"(b[1]));
}
__device__ __forceinline__ void ldsm4(uint32_t& r0, uint32_t& r1, uint32_t& r2, uint32_t& r3,
                                      uint32_t addr) {
    asm volatile("ldmatrix.sync.aligned.m8n8.x4.shared.b16 {%0,%1,%2,%3}, [%4];"
        : "=r"(r0), "=r"(r1), "=r"(r2), "=r"(r3) : "r"(addr));
}
__device__ __forceinline__ void ldsm4t(uint32_t& r0, uint32_t& r1, uint32_t& r2, uint32_t& r3,
                                       uint32_t addr) {
    asm volatile("ldmatrix.sync.aligned.m8n8.x4.trans.shared.b16 {%0,%1,%2,%3}, [%4];"
        : "=r"(r0), "=r"(r1), "=r"(r2), "=r"(r3) : "r"(addr));
}
__device__ __forceinline__ void cpa16(__half* dst, const __half* src) {
    uint32_t d = (uint32_t)__cvta_generic_to_shared(dst);
    asm volatile("cp.async.cg.shared.global [%0], [%1], 16;" :: "r"(d), "l"(src));
}

// ---------------- kernel 1: fused avg+max 3x3 pooling ----------------------
__global__ void __launch_bounds__(256) pool_kernel(const float* __restrict__ x) {
    __shared__ float tile[9216];
    const float4* s4 = reinterpret_cast<const float4*>(x + (size_t)blockIdx.x * 9216);
    float4* t4 = reinterpret_cast<float4*>(tile);
    #pragma unroll
    for (int i = 0; i < 9; i++)
        t4[threadIdx.x + i*256] = s4[threadIdx.x + i*256];
    __syncthreads();
    size_t base = (size_t)blockIdx.x * 1024;
    #pragma unroll
    for (int it = 0; it < 4; it++) {
        int sp = threadIdx.x + it*256;
        int r1 = sp >> 5, r2 = sp & 31;
        const float* p = &tile[r1*3*96 + r2*3];
        float s = 0.f, m = NEG_INF;
        #pragma unroll
        for (int i = 0; i < 3; i++)
            #pragma unroll
            for (int j = 0; j < 3; j++) {
                float v = p[i*96 + j];
                s += v;
                m = fmaxf(m, v);
            }
        float a = s * (1.f/9.f);
        g_qpool [base + sp] = a;
        g_qpoolh[base + sp] = __float2half_rn(a);
        g_kpoolh[base + sp] = __float2half_rn(m);
    }
}

// ---------------- init + weight conversion -----------------------------------
__global__ void init_kernel() {
    int i = blockIdx.x * 256 + threadIdx.x;
    g_sumexp[i] = 0.f;
    if (i < B_*HN_*D_) g_kmean[i] = 0.f;
}
__global__ void cvt_kernel(const float* __restrict__ src, __half* __restrict__ dst) {
    int i = blockIdx.x * 256 + threadIdx.x;
    dst[i] = __float2half_rn(src[i]);
}

// ---------------- fp16 tensor-core GEMM, 128x128 tile, K-chunk 32, 4 stages --
// MODE 0: C(h) = acc + bias
// MODE 1: C(h) = acc + bias, atomicAdd row sums into raux1[z*M+m]
// MODE 2: C(h) = exp(acc * raux2[z*M+m]) * 2^-4, atomicAdd row sums -> raux1
// MODE 3: C(f32) = resid + acc * (1/raux2[z*N+n]) * (1 + *wptr)
// smem layouts (fp16 units):
//   outer-major: 128 rows x 32 k, stride 40  (MK / NK)
//   k-major:      32 rows x 128,  stride 136 (KM / KN)
template<bool A_KM, bool B_NK, int MODE>
__global__ void __launch_bounds__(256) mm_f16(
    const __half* __restrict__ A, const __half* __restrict__ Bm,
    const float* __restrict__ bias, void* __restrict__ Cc,
    int M, int N, int K,
    int aMod, long long aStride, long long bStride, long long cStride,
    int biasMod, int biasStride,
    float* __restrict__ raux1, const float* __restrict__ raux2,
    const float* __restrict__ resid, const int* __restrict__ wptr)
{
    constexpr int STAGES = 4;
    constexpr int AW = A_KM ? 32*136 : 128*40;   // fp16 units per stage
    constexpr int BW = B_NK ? 128*40 : 32*136;
    extern __shared__ __half dsm[];
    __half* As = dsm;
    __half* Bs = dsm + STAGES*AW;
    __shared__ float sS[128];

    const int z = blockIdx.z;
    A  += (size_t)(z % aMod) * aStride;
    Bm += (size_t)z * bStride;

    const int bm = blockIdx.y * 128;
    const int bn = blockIdx.x * 128;
    const int tid  = threadIdx.x;
    const int lane = tid & 31;
    const int warp = tid >> 5;
    const int wm = warp >> 1;
    const int wn = warp & 1;
    const int qr = lane >> 2;
    const int cq = lane & 3;

    float acc[2][8][4];
    #pragma unroll
    for (int i = 0; i < 2; i++)
        #pragma unroll
        for (int j = 0; j < 8; j++)
            #pragma unroll
            for (int k = 0; k < 4; k++) acc[i][j][k] = 0.f;

    auto issue = [&](int t) {
        int buf = t & (STAGES-1);
        int k0 = t << 5;
        __half* Ab = As + buf*AW;
        __half* Bb = Bs + buf*BW;
        if (A_KM) {
            int k = tid >> 4, c = tid & 15;
            cpa16(Ab + k*136 + c*8,       A + (size_t)(k0+k)   *M + bm + c*8);
            cpa16(Ab + (k+16)*136 + c*8,  A + (size_t)(k0+k+16)*M + bm + c*8);
        } else {
            int m = tid >> 2, c = tid & 3;
            cpa16(Ab + m*40 + c*8,        A + (size_t)(bm+m)   *K + k0 + c*8);
            cpa16(Ab + (m+64)*40 + c*8,   A + (size_t)(bm+m+64)*K + k0 + c*8);
        }
        if (B_NK) {
            int n = tid >> 2, c = tid & 3;
            cpa16(Bb + n*40 + c*8,        Bm + (size_t)(bn+n)   *K + k0 + c*8);
            cpa16(Bb + (n+64)*40 + c*8,   Bm + (size_t)(bn+n+64)*K + k0 + c*8);
        } else {
            int k = tid >> 4, c = tid & 15;
            cpa16(Bb + k*136 + c*8,       Bm + (size_t)(k0+k)   *N + bn + c*8);
            cpa16(Bb + (k+16)*136 + c*8,  Bm + (size_t)(k0+k+16)*N + bn + c*8);
        }
        asm volatile("cp.async.commit_group;" ::: "memory");
    };

    const uint32_t aSm = (uint32_t)__cvta_generic_to_shared(As);
    const uint32_t bSm = (uint32_t)__cvta_generic_to_shared(Bs);

    auto compute = [&](int buf) {
        const uint32_t aBase = aSm + buf*AW*2;
        const uint32_t bBase = bSm + buf*BW*2;
        #pragma unroll
        for (int kk = 0; kk < 32; kk += 16) {
            uint32_t af[2][4], bf[8][2];
            #pragma unroll
            for (int mt = 0; mt < 2; mt++) {
                if (A_KM) {
                    uint32_t ad = aBase +
                        (((kk + (lane&7) + ((lane&16)>>1)) * 136) +
                          wm*32 + mt*16 + (lane&8)) * 2;
                    ldsm4t(af[mt][0], af[mt][1], af[mt][2], af[mt][3], ad);
                } else {
                    uint32_t ad = aBase +
                        (((wm*32 + mt*16 + (lane&15)) * 40) +
                          kk + ((lane&16)>>1)) * 2;
                    ldsm4(af[mt][0], af[mt][1], af[mt][2], af[mt][3], ad);
                }
            }
            #pragma unroll
            for (int j = 0; j < 4; j++) {
                if (B_NK) {
                    uint32_t bd = bBase +
                        (((wn*64 + j*16 + (lane&7) + ((lane&16)>>1)) * 40) +
                          kk + (lane&8)) * 2;
                    ldsm4(bf[2*j][0], bf[2*j][1], bf[2*j+1][0], bf[2*j+1][1], bd);
                } else {
                    uint32_t bd = bBase +
                        (((kk + (lane&7) + (lane&8)) * 136) +
                          wn*64 + j*16 + ((lane&16)>>1)) * 2;
                    ldsm4t(bf[2*j][0], bf[2*j][1], bf[2*j+1][0], bf[2*j+1][1], bd);
                }
            }
            #pragma unroll
            for (int mt = 0; mt < 2; mt++)
                #pragma unroll
                for (int nt = 0; nt < 8; nt++)
                    mma_f16(acc[mt][nt], af[mt], bf[nt]);
        }
    };

    // ---- pipelined main loop ----
    const int nT = K >> 5;
    #pragma unroll
    for (int s = 0; s < STAGES-1; s++) issue(s);
    if (MODE == 3 && tid < 128)
        sS[tid] = 1.f / raux2[(size_t)z * N + bn + tid];
    for (int t = 0; t < nT; t++) {
        asm volatile("cp.async.wait_group 2;" ::: "memory");
        __syncthreads();
        if (t + STAGES-1 < nT) issue(t + STAGES-1);
        else asm volatile("cp.async.commit_group;" ::: "memory");
        compute(t & (STAGES-1));
    }

    // ---- epilogue ----
    __half* Ch = (__half*)Cc + (MODE == 3 ? 0 : (size_t)z * cStride);
    float*  Cf = (float*)Cc + (size_t)z * cStride;
    const float* rz = (MODE == 3) ? resid + (size_t)z * cStride : nullptr;
    const float ws = (MODE == 3) ? (1.f + (float)wptr[0]) : 0.f;
    #pragma unroll
    for (int mt = 0; mt < 2; mt++) {
        int row0 = bm + wm*32 + mt*16 + qr;
        float b0 = 0.f, b1 = 0.f;
        if (MODE <= 1) {
            const float* bptr = bias + (size_t)(z % biasMod) * biasStride;
            b0 = bptr[row0]; b1 = bptr[row0 + 8];
        }
        float sc0 = 0.f, sc1 = 0.f;
        if (MODE == 2) {
            sc0 = raux2[(size_t)z * M + row0];
            sc1 = raux2[(size_t)z * M + row0 + 8];
        }
        float s0 = 0.f, s1 = 0.f;
        #pragma unroll
        for (int nt = 0; nt < 8; nt++) {
            int col = bn + wn*64 + nt*8 + cq*2;
            float* d = acc[mt][nt];
            if (MODE == 3) {
                int lc = wn*64 + nt*8 + cq*2;
                float i0 = sS[lc], i1 = sS[lc+1];
                float2 rv0 = *(const float2*)&rz[(size_t)row0    *N + col];
                float2 rv1 = *(const float2*)&rz[(size_t)(row0+8)*N + col];
                *(float2*)&Cf[(size_t)row0    *N + col] =
                    make_float2(rv0.x + d[0]*i0*ws, rv0.y + d[1]*i1*ws);
                *(float2*)&Cf[(size_t)(row0+8)*N + col] =
                    make_float2(rv1.x + d[2]*i0*ws, rv1.y + d[3]*i1*ws);
            } else if (MODE == 2) {
                float v0 = __expf(d[0]*sc0)*0.0625f, v1 = __expf(d[1]*sc0)*0.0625f;
                float v2 = __expf(d[2]*sc1)*0.0625f, v3 = __expf(d[3]*sc1)*0.0625f;
                *(__half2*)&Ch[(size_t)row0    *N + col] = __floats2half2_rn(v0, v1);
                *(__half2*)&Ch[(size_t)(row0+8)*N + col] = __floats2half2_rn(v2, v3);
                s0 += v0 + v1; s1 += v2 + v3;
            } else {
                *(__half2*)&Ch[(size_t)row0    *N + col] = __floats2half2_rn(d[0]+b0, d[1]+b0);
                *(__half2*)&Ch[(size_t)(row0+8)*N + col] = __floats2half2_rn(d[2]+b1, d[3]+b1);
                if (MODE == 1) { s0 += d[0] + d[1] + 2.f*b0; s1 += d[2] + d[3] + 2.f*b1; }
            }
        }
        if (MODE == 1 || MODE == 2) {
            s0 += __shfl_xor_sync(0xffffffffu, s0, 1);
            s0 += __shfl_xor_sync(0xffffffffu, s0, 2);
            s1 += __shfl_xor_sync(0xffffffffu, s1, 1);
            s1 += __shfl_xor_sync(0xffffffffu, s1, 2);
            if (cq == 0) {
                atomicAdd(&raux1[(size_t)z * M + row0],     s0);
                atomicAdd(&raux1[(size_t)z * M + row0 + 8], s1);
            }
        }
    }
}

// ---------------- kernel: kmean x Qt -> p gate -> row scale ------------------
// rowmean[c] = mean_e' S[c,e'] = sum_e Qt[e,c] * kmean[e]   (exact identity)
__global__ void __launch_bounds__(512) pgate_kernel(const float* __restrict__ Wp,
                                                    const float* __restrict__ bp) {
    const int z = blockIdx.x;
    __shared__ float km[128];
    __shared__ float msh[512];
    const int tid = threadIdx.x;
    if (tid < 128) km[tid] = g_kmean[(size_t)z * 128 + tid] * (1.f/512.f);
    __syncthreads();

    const __half* Qz = g_Qth + (size_t)z * 65536;
    float rm = 0.f;
    #pragma unroll 4
    for (int e = 0; e < 128; e++)
        rm = fmaf(__half2float(Qz[(size_t)e * 512 + tid]), km[e], rm);
    msh[tid] = rm;
    __syncthreads();

    float accv = bp[tid];
    const float* wrow = Wp + (size_t)tid * 512;
    #pragma unroll 4
    for (int j = 0; j < 512; j++) accv = fmaf(msh[j], wrow[j], accv);
    float p = 1.f / (1.f + expf(-accv));
    g_rowscale[(size_t)z * 512 + tid] = exp2f(-7.f * (0.5f + p));   // D^{-(0.5+p)}
}

// ---------------- launch ----------------------------------------------------
extern "C" void kernel_launch(void* const* d_in, const int* in_sizes, int n_in,
                              void* d_out, int out_size) {
    const float* x   = (const float*)d_in[0];
    const float* Wqk = (const float*)d_in[1];
    const float* bqk = (const float*)d_in[2];
    const float* Wp  = (const float*)d_in[3];
    const float* bp  = (const float*)d_in[4];
    const float* Wv  = (const float*)d_in[5];
    const float* bv  = (const float*)d_in[6];
    const int*   wgt = (const int*)d_in[7];
    float* out = (float*)d_out;

    float *qpool, *kmean, *sumexp, *rowscale;
    __half *qpoolh, *kpoolh, *vpoolh, *Qth, *Kth, *Sh, *Wvh, *Wqkh;
    cudaGetSymbolAddress((void**)&qpool,    g_qpool);
    cudaGetSymbolAddress((void**)&qpoolh,   g_qpoolh);
    cudaGetSymbolAddress((void**)&kpoolh,   g_kpoolh);
    cudaGetSymbolAddress((void**)&vpoolh,   g_vpoolh);
    cudaGetSymbolAddress((void**)&Qth,      g_Qth);
    cudaGetSymbolAddress((void**)&Kth,      g_Kth);
    cudaGetSymbolAddress((void**)&Sh,       g_Sh);
    cudaGetSymbolAddress((void**)&Wvh,      g_Wvh);
    cudaGetSymbolAddress((void**)&Wqkh,     g_Wqkh);
    cudaGetSymbolAddress((void**)&kmean,    g_kmean);
    cudaGetSymbolAddress((void**)&sumexp,   g_sumexp);
    cudaGetSymbolAddress((void**)&rowscale, g_rowscale);

    cudaFuncSetAttribute(mm_f16<false,false,0>, cudaFuncAttributeMaxDynamicSharedMemorySize, 75776);
    cudaFuncSetAttribute(mm_f16<false,false,1>, cudaFuncAttributeMaxDynamicSharedMemorySize, 75776);
    cudaFuncSetAttribute(mm_f16<true, false,2>, cudaFuncAttributeMaxDynamicSharedMemorySize, 69632);
    cudaFuncSetAttribute(mm_f16<false,true, 3>, cudaFuncAttributeMaxDynamicSharedMemorySize, 81920);

    // 0) weight conversion to fp16; init reductions
    cvt_kernel<<<1024, 256>>>(Wv,  Wvh);    // 512*512
    cvt_kernel<<< 512, 256>>>(Wqk, Wqkh);   // 8*128*128
    init_kernel<<<256, 256>>>();

    // 1) fused avg/max pooling: x -> qpool(f32), qpool_h, kpool_h
    pool_kernel<<<8192, 256>>>(x);

    // 2) vpool_h[b] = Wv @ qpool[b] + bv   (1x1 conv & avgpool commute)
    mm_f16<false,false,0><<<dim3(8,4,16), 256, 75776>>>(
        Wvh, qpoolh, bv, vpoolh, 512, 1024, 512,
        1, 0, 524288, 524288, 1, 0, nullptr, nullptr, nullptr, nullptr);

    // 3) Kt[z] = Wqk[h] @ kpool_block[z] + bqk[h]  (+ fused row sums -> kmean)
    mm_f16<false,false,1><<<dim3(4,1,128), 256, 75776>>>(
        Wqkh, kpoolh, bqk, Kth, 128, 512, 128,
        8, 16384, 65536, 65536, 8, 128, kmean, nullptr, nullptr, nullptr);

    // 4) Qt[z] = Wqk[h] @ qpool_block[z] + bqk[h]
    mm_f16<false,false,0><<<dim3(4,1,128), 256, 75776>>>(
        Wqkh, qpoolh, bqk, Qth, 128, 512, 128,
        8, 16384, 65536, 65536, 8, 128, nullptr, nullptr, nullptr, nullptr);

    // 5) gate: rowmean = Qt . kmean -> sigmoid -> rowscale (before scores!)
    pgate_kernel<<<128, 512>>>(Wp, bp);

    // 6) S[z] = exp((Qt[z]^T @ Kt[z]) * rowscale) * 2^-4  (+ fused sumexp)
    //    (scores provably small; softmax shift-invariance makes no-max exact;
    //     2^-4 scaling keeps fp16 storage far from overflow and cancels below)
    mm_f16<true,false,2><<<dim3(4,4,128), 256, 69632>>>(
        Qth, Kth, nullptr, Sh, 512, 512, 128,
        1<<30, 65536, 65536, 262144, 1, 0, sumexp, rowscale, nullptr, nullptr);

    // 7) out[z] = qpool[z] + (V @ expS^T) * (1/sumexp) * (1+weight)
    mm_f16<false,true,3><<<dim3(4,1,128), 256, 81920>>>(
        vpoolh, Sh, nullptr, out, 128, 512, 512,
        1<<30, 65536, 262144, 65536, 1, 0, nullptr, sumexp, qpool, wgt);
}